// round 15
// baseline (speedup 1.0000x reference)
#include <cuda_runtime.h>
#include <cuda_bf16.h>

#define B_    8192
#define NPAIR 32
#define BN    (B_ * NPAIR)
#define RREL  3
#define KP    136            // padded bf16 row stride (conflict-free for ldmatrix)
#define CH    32             // items per chunk (per warp-group)

__device__ float g_ui[B_ * 64];
__device__ int   g_cnt[RREL];
__device__ int   g_items[RREL * BN];

__device__ __forceinline__ float lrelu(float x) { return x >= 0.f ? x : 0.01f * x; }

// Truncation-based 2-way bf16 split: hi = bit-truncated bf16 (exact residual),
// lo = rn(x - hi). Pair error <= 2^-17 |x|.
__device__ __forceinline__ void split2(float x0, float x1, unsigned& hi, unsigned& lo) {
    unsigned u0 = __float_as_uint(x0), u1 = __float_as_uint(x1);
    hi = __byte_perm(u0, u1, 0x7632);
    float l0 = x0 - __uint_as_float(u0 & 0xFFFF0000u);
    float l1 = x1 - __uint_as_float(u1 & 0xFFFF0000u);
    asm("cvt.rn.bf16x2.f32 %0, %1, %2;" : "=r"(lo) : "f"(l1), "f"(l0));
}

__device__ __forceinline__ unsigned smem_u32(const void* p) {
    unsigned a;
    asm("{ .reg .u64 t; cvta.to.shared.u64 t, %1; cvt.u32.u64 %0, t; }" : "=r"(a) : "l"(p));
    return a;
}

#define MMA(d, a, b) \
    asm volatile("mma.sync.aligned.m16n8k16.row.col.f32.bf16.bf16.f32 " \
        "{%0,%1,%2,%3}, {%4,%5,%6,%7}, {%8,%9}, {%0,%1,%2,%3};" \
        : "+f"((d)[0]), "+f"((d)[1]), "+f"((d)[2]), "+f"((d)[3]) \
        : "r"((a)[0]), "r"((a)[1]), "r"((a)[2]), "r"((a)[3]), "r"((b)[0]), "r"((b)[1]))

#define LDSM4(r0, r1, r2, r3, addr) \
    asm volatile("ldmatrix.sync.aligned.m8n8.x4.shared.b16 {%0,%1,%2,%3}, [%4];" \
        : "=r"(r0), "=r"(r1), "=r"(r2), "=r"(r3) : "r"(addr))

#define BARG(id) asm volatile("bar.sync %0, 256;" :: "r"(id) : "memory")
#define CP_ASYNC16(dst, src) \
    asm volatile("cp.async.cg.shared.global [%0], [%1], 16;" :: "r"(dst), "l"(src))
#define CP_COMMIT() asm volatile("cp.async.commit_group;" ::: "memory")
#define CP_WAIT0()  asm volatile("cp.async.wait_group 0;" ::: "memory")

// ---------------- kernel A: ui branch (unchanged, passing) ----------------
__global__ __launch_bounds__(128) void ui_kernel(
    const float* __restrict__ u, const float* __restrict__ iv,
    const float* __restrict__ W0, const float* __restrict__ b0,
    const float* __restrict__ W1, const float* __restrict__ b1)
{
    __shared__ float sx[8][128];
    __shared__ float sh[8][128];
    int tid = threadIdx.x;
    int row0 = blockIdx.x * 8;
    #pragma unroll
    for (int rr = 0; rr < 8; rr++) {
        int row = row0 + rr;
        sx[rr][tid] = (tid < 64) ? u[row * 64 + tid] : iv[row * 64 + tid - 64];
    }
    __syncthreads();
    float acc[8];
    #pragma unroll
    for (int rr = 0; rr < 8; rr++) acc[rr] = 0.f;
    #pragma unroll 4
    for (int k = 0; k < 128; k++) {
        float w = W0[k * 128 + tid];
        #pragma unroll
        for (int rr = 0; rr < 8; rr++) acc[rr] += sx[rr][k] * w;
    }
    float bb = b0[tid];
    #pragma unroll
    for (int rr = 0; rr < 8; rr++) sh[rr][tid] = lrelu(acc[rr] + bb);
    __syncthreads();
    int j = tid & 63, rb = (tid >> 6) * 4;
    float a2[4] = {0.f, 0.f, 0.f, 0.f};
    #pragma unroll 4
    for (int k = 0; k < 128; k++) {
        float w = W1[k * 64 + j];
        #pragma unroll
        for (int q = 0; q < 4; q++) a2[q] += sh[rb + q][k] * w;
    }
    float b2 = b1[j];
    #pragma unroll
    for (int q = 0; q < 4; q++) g_ui[(row0 + rb + q) * 64 + j] = lrelu(a2[q] + b2);
}

// ---------------- zero + bin kernels ----------------
__global__ void zero_cnt_kernel() {
    if (threadIdx.x < RREL) g_cnt[threadIdx.x] = 0;
}

__global__ __launch_bounds__(512) void bin_kernel(const void* __restrict__ s_raw)
{
    __shared__ int bc[RREL], bb[RREL], sis64;
    int tid = threadIdx.x;
    if (tid == 0) {
        const int* p = (const int*)s_raw;
        int any = 0;
        for (int q = 1; q < 257; q += 2) any |= p[q];
        sis64 = (any == 0);
        bc[0] = bc[1] = bc[2] = 0;
    }
    __syncthreads();
    int it = blockIdx.x * 512 + tid;
    const int* s32 = (const int*)s_raw;
    int sv = sis64 ? s32[2 * it] : s32[it];
    sv = min(max(sv, 0), RREL - 1);
    int pos = atomicAdd(&bc[sv], 1);
    __syncthreads();
    if (tid < RREL) bb[tid] = atomicAdd(&g_cnt[tid], bc[tid]);
    __syncthreads();
    g_items[sv * BN + bb[sv] + pos] = it;
}

// ---------------- kernel C: cp.async-pipelined bf16 mma AO branch ----------------
// smem map (bytes):
//   X: grp g at g*17408: XH 32x136 bf16 (8704) + XL (8704)         [0, 34816)
//   W0H 34816 (34816), W0L 69632 (34816)
//   W1H 104448 (17408), W1L 121856 (17408)
//   stage: grp g at 139264 + g*16384 (32 rows x 512B fp32)         [139264, 171?]
//   sb0 172032 (512), sb1 172544 (256), sl 172800 (2x32 int), sred 173056 (2x512B)
#define XGRP      17408
#define XHALF     8704
#define W0H_OFF   34816
#define W0L_OFF   69632
#define W1H_OFF   104448
#define W1L_OFF   121856
#define STG_OFF   139264
#define STG_GRP   16384
#define SB0_OFF   172032
#define SB1_OFF   172544
#define SL_OFF    172800
#define SRED_OFF  173056
#define SMEM_TOT  174080

#define ROWSTEP16 (16 * KP * 2)   // 4352 bytes (16 weight rows)

__global__ __launch_bounds__(512, 1) void ao_mma_kernel(
    const float* __restrict__ a_emb, const float* __restrict__ o_emb,
    const float* __restrict__ aoW0, const float* __restrict__ aob0,
    const float* __restrict__ aoW1, const float* __restrict__ aob1,
    float* __restrict__ out)
{
    extern __shared__ char smem[];
    unsigned sbase = smem_u32(smem);
    float* sb0 = (float*)(smem + SB0_OFF);
    float* sb1 = (float*)(smem + SB1_OFF);

    int tid = threadIdx.x, wid = tid >> 5, lane = tid & 31;
    int grp = wid >> 3;
    int wg  = wid & 7;
    int tg  = tid & 255;
    int gq = lane >> 2, t = lane & 3;
    int barid = 1 + grp;

    int*   slg   = (int*)(smem + SL_OFF) + grp * 32;
    float* sredg = (float*)(smem + SRED_OFF) + grp * 128;

    unsigned rowSel = (unsigned)(lane & 15);
    unsigned kSel   = (unsigned)((lane >> 4) << 3);

    // warp tiles: GEMM1 16x32 (2 m-tiles x 4 n-tiles), GEMM2 16x16 (2 x 4)
    int mrow  = (wg & 1) * 16;
    int ncol  = (wg >> 1) * 32;
    int ncol2 = (wg >> 1) * 16;

    unsigned xbase = sbase + (unsigned)grp * XGRP;
    unsigned aHiB  = xbase + ((mrow + rowSel) * KP + kSel) * 2;
    unsigned aLoB  = aHiB + XHALF;
    unsigned b0HiB = sbase + W0H_OFF + ((ncol + rowSel) * KP + kSel) * 2;
    unsigned b0LoB = b0HiB + (W0L_OFF - W0H_OFF);
    unsigned b1HiB = sbase + W1H_OFF + ((ncol2 + rowSel) * KP + kSel) * 2;
    unsigned b1LoB = b1HiB + (W1L_OFF - W1H_OFF);
    unsigned stgB  = sbase + STG_OFF + (unsigned)grp * STG_GRP;
    char*    stgP  = smem + STG_OFF + grp * STG_GRP;

    int cnt[RREL], rs[RREL + 1];
    rs[0] = 0;
    #pragma unroll
    for (int r = 0; r < RREL; r++) {
        cnt[r] = g_cnt[r];
        rs[r + 1] = rs[r] + ((cnt[r] + CH - 1) / CH);
    }
    int tot = rs[RREL];
    int per = (tot + gridDim.x - 1) / gridDim.x;
    int c_lo = blockIdx.x * per, c_hi = min(tot, c_lo + per);

    for (int r = 0; r < RREL; r++) {
        int lo = max(c_lo, rs[r]), hi = min(c_hi, rs[r + 1]);
        if (lo >= hi) continue;
        int rOff = r * BN, cntR = cnt[r];

        // ---- cooperative weight staging (whole CTA) ----
        {
            const float* w0g = aoW0 + (size_t)r * 16384;
            for (int idx = tid; idx < 8192; idx += 512) {
                int n = idx & 127, k = (idx >> 7) * 2;
                unsigned hi_, lo_;
                split2(w0g[k * 128 + n], w0g[(k + 1) * 128 + n], hi_, lo_);
                *(unsigned*)(smem + W0H_OFF + (n * KP + k) * 2) = hi_;
                *(unsigned*)(smem + W0L_OFF + (n * KP + k) * 2) = lo_;
            }
            const float* w1g = aoW1 + (size_t)r * 8192;
            for (int idx = tid; idx < 4096; idx += 512) {
                int o = idx & 63, h = (idx >> 6) * 2;
                unsigned hi_, lo_;
                split2(w1g[h * 64 + o], w1g[(h + 1) * 64 + o], hi_, lo_);
                *(unsigned*)(smem + W1H_OFF + (o * KP + h) * 2) = hi_;
                *(unsigned*)(smem + W1L_OFF + (o * KP + h) * 2) = lo_;
            }
            if (tid < 128) sb0[tid] = aob0[r * 128 + tid];
            if (tid < 64)  sb1[tid] = aob1[r * 64 + tid];
        }
        __syncthreads();

        // ---- prologue: prefetch this group's first chunk ----
        int c0 = lo + grp;
        if (c0 < hi) {
            int base = (c0 - rs[r]) * CH;
            #pragma unroll
            for (int j = 0; j < 4; j++) {
                int idx = tg + j * 256;
                int row = idx >> 5, s = idx & 31;
                int item = base + row;
                int g = (item < cntR) ? g_items[rOff + item] : 0;
                const float* src = (s < 16) ? a_emb + (size_t)g * 64 + s * 4
                                            : o_emb + (size_t)g * 64 + (s - 16) * 4;
                CP_ASYNC16(stgB + row * 512 + s * 16, src);
            }
        }
        CP_COMMIT();

        // ---- chunk loop (groups interleave; each pipelines its own chunks) ----
        for (int c = c0; c < hi; c += 2) {
            int ci = c - rs[r];
            int base = ci * CH;
            int valid = min(CH, cntR - base);

            if (tg < 32) slg[tg] = (tg < valid) ? g_items[rOff + base + tg] : -1;

            CP_WAIT0();
            BARG(barid);

            // ---- convert: stage fp32 -> split bf16 hi/lo (stall-free LDS path) ----
            {
                int crow0 = wg * 4;
                #pragma unroll
                for (int i = 0; i < 4; i++) {
                    int row = crow0 + i;
                    float4 v = *(const float4*)(stgP + row * 512 + lane * 16);
                    unsigned h0, l0, h1, l1;
                    split2(v.x, v.y, h0, l0);
                    split2(v.z, v.w, h1, l1);
                    unsigned d = (unsigned)(grp * XGRP) + (row * KP + lane * 4) * 2;
                    *(uint2*)(smem + d)         = make_uint2(h0, h1);
                    *(uint2*)(smem + d + XHALF) = make_uint2(l0, l1);
                }
            }
            BARG(barid);

            // ---- issue prefetch for chunk c+2 (lands during GEMMs) ----
            {
                int cn = c + 2;
                if (cn < hi) {
                    int bn = (cn - rs[r]) * CH;
                    #pragma unroll
                    for (int j = 0; j < 4; j++) {
                        int idx = tg + j * 256;
                        int row = idx >> 5, s = idx & 31;
                        int item = bn + row;
                        int g = (item < cntR) ? g_items[rOff + item] : 0;
                        const float* src = (s < 16) ? a_emb + (size_t)g * 64 + s * 4
                                                    : o_emb + (size_t)g * 64 + (s - 16) * 4;
                        CP_ASYNC16(stgB + row * 512 + s * 16, src);
                    }
                }
                CP_COMMIT();
            }

            // ---- GEMM1: D1[32,128] = X @ W0 (3-term split) ----
            float acc[4][4];
            #pragma unroll
            for (int j = 0; j < 4; j++)
                #pragma unroll
                for (int q = 0; q < 4; q++) acc[j][q] = 0.f;

            #pragma unroll
            for (int kt = 0; kt < 8; kt++) {
                unsigned ko = (unsigned)kt * 32;
                unsigned ah[4], al[4], bh[4][2], bl[4][2];
                LDSM4(ah[0], ah[1], ah[2], ah[3], aHiB + ko);
                LDSM4(al[0], al[1], al[2], al[3], aLoB + ko);
                {
                    unsigned r0, r1, r2, r3;
                    LDSM4(r0, r1, r2, r3, b0HiB + ko);
                    bh[0][0] = r0; bh[1][0] = r1; bh[0][1] = r2; bh[1][1] = r3;
                    LDSM4(r0, r1, r2, r3, b0HiB + ROWSTEP16 + ko);
                    bh[2][0] = r0; bh[3][0] = r1; bh[2][1] = r2; bh[3][1] = r3;
                    LDSM4(r0, r1, r2, r3, b0LoB + ko);
                    bl[0][0] = r0; bl[1][0] = r1; bl[0][1] = r2; bl[1][1] = r3;
                    LDSM4(r0, r1, r2, r3, b0LoB + ROWSTEP16 + ko);
                    bl[2][0] = r0; bl[3][0] = r1; bl[2][1] = r2; bl[3][1] = r3;
                }
                #pragma unroll
                for (int na = 0; na < 4; na++) MMA(acc[na], ah, bh[na]);
                #pragma unroll
                for (int na = 0; na < 4; na++) MMA(acc[na], ah, bl[na]);
                #pragma unroll
                for (int na = 0; na < 4; na++) MMA(acc[na], al, bh[na]);
            }
            BARG(barid);   // all X reads done before overwrite with H

            // ---- epilogue 1: H = lrelu(D1 + b0), split in place of X ----
            {
                int rr0 = mrow + gq;
                #pragma unroll
                for (int na = 0; na < 4; na++) {
                    int cc = ncol + na * 8 + 2 * t;
                    float h0 = lrelu(acc[na][0] + sb0[cc]);
                    float h1 = lrelu(acc[na][1] + sb0[cc + 1]);
                    float h2 = lrelu(acc[na][2] + sb0[cc]);
                    float h3 = lrelu(acc[na][3] + sb0[cc + 1]);
                    unsigned hi_, lo_;
                    unsigned d = (unsigned)(grp * XGRP) + (rr0 * KP + cc) * 2;
                    split2(h0, h1, hi_, lo_);
                    *(unsigned*)(smem + d)         = hi_;
                    *(unsigned*)(smem + d + XHALF) = lo_;
                    split2(h2, h3, hi_, lo_);
                    unsigned d2 = d + 8 * KP * 2;
                    *(unsigned*)(smem + d2)         = hi_;
                    *(unsigned*)(smem + d2 + XHALF) = lo_;
                }
            }
            BARG(barid);

            // ---- hoist ui loads (L2 latency covered by GEMM2) ----
            int rowA = mrow + gq, rowB = rowA + 8;
            int gA = slg[rowA], gB = slg[rowB];
            const float* uiA = g_ui + (size_t)(max(gA, 0) >> 5) * 64;
            const float* uiB = g_ui + (size_t)(max(gB, 0) >> 5) * 64;
            float2 uvA[2], uvB[2];
            #pragma unroll
            for (int na = 0; na < 2; na++) {
                int cc = ncol2 + na * 8 + 2 * t;
                uvA[na] = *(const float2*)(uiA + cc);
                uvB[na] = *(const float2*)(uiB + cc);
            }

            // ---- GEMM2: D2[32,64] = H @ W1 ----
            float acc2[2][4];
            #pragma unroll
            for (int j = 0; j < 2; j++)
                #pragma unroll
                for (int q = 0; q < 4; q++) acc2[j][q] = 0.f;

            #pragma unroll
            for (int kt = 0; kt < 8; kt++) {
                unsigned ko = (unsigned)kt * 32;
                unsigned ah[4], al[4], bh[2][2], bl[2][2];
                LDSM4(ah[0], ah[1], ah[2], ah[3], aHiB + ko);
                LDSM4(al[0], al[1], al[2], al[3], aLoB + ko);
                {
                    unsigned r0, r1, r2, r3;
                    LDSM4(r0, r1, r2, r3, b1HiB + ko);
                    bh[0][0] = r0; bh[1][0] = r1; bh[0][1] = r2; bh[1][1] = r3;
                    LDSM4(r0, r1, r2, r3, b1LoB + ko);
                    bl[0][0] = r0; bl[1][0] = r1; bl[0][1] = r2; bl[1][1] = r3;
                }
                #pragma unroll
                for (int na = 0; na < 2; na++) MMA(acc2[na], ah, bh[na]);
                #pragma unroll
                for (int na = 0; na < 2; na++) MMA(acc2[na], ah, bl[na]);
                #pragma unroll
                for (int na = 0; na < 2; na++) MMA(acc2[na], al, bh[na]);
            }

            // ---- epilogue 2: o = lrelu(D2 + b1); dot with ui; reduce ----
            {
                float pA = 0.f, pB = 0.f;
                #pragma unroll
                for (int na = 0; na < 2; na++) {
                    int cc = ncol2 + na * 8 + 2 * t;
                    float oA0 = lrelu(acc2[na][0] + sb1[cc]);
                    float oA1 = lrelu(acc2[na][1] + sb1[cc + 1]);
                    float oB0 = lrelu(acc2[na][2] + sb1[cc]);
                    float oB1 = lrelu(acc2[na][3] + sb1[cc + 1]);
                    pA += oA0 * uvA[na].x + oA1 * uvA[na].y;
                    pB += oB0 * uvB[na].x + oB1 * uvB[na].y;
                }
                pA += __shfl_xor_sync(0xffffffffu, pA, 1);
                pA += __shfl_xor_sync(0xffffffffu, pA, 2);
                pB += __shfl_xor_sync(0xffffffffu, pB, 1);
                pB += __shfl_xor_sync(0xffffffffu, pB, 2);
                if (t == 0) {
                    sredg[rowA * 4 + (wg >> 1)] = pA;
                    sredg[rowB * 4 + (wg >> 1)] = pB;
                }
            }
            BARG(barid);
            if (tg < 32) {
                int g = slg[tg];
                if (g >= 0)
                    out[g] = sredg[tg * 4] + sredg[tg * 4 + 1]
                           + sredg[tg * 4 + 2] + sredg[tg * 4 + 3];
            }
            BARG(barid);
        }
        __syncthreads();
    }
}

// ---------------- launch ----------------
extern "C" void kernel_launch(void* const* d_in, const int* in_sizes, int n_in,
                              void* d_out, int out_size)
{
    const float* u    = (const float*)d_in[0];
    const float* iv   = (const float*)d_in[1];
    const float* a    = (const float*)d_in[2];
    const float* o    = (const float*)d_in[3];
    const void*  s    = d_in[4];
    const float* aoW0 = (const float*)d_in[5];
    const float* aob0 = (const float*)d_in[6];
    const float* aoW1 = (const float*)d_in[7];
    const float* aob1 = (const float*)d_in[8];
    const float* uiW0 = (const float*)d_in[9];
    const float* uib0 = (const float*)d_in[10];
    const float* uiW1 = (const float*)d_in[11];
    const float* uib1 = (const float*)d_in[12];
    float* out = (float*)d_out;

    cudaFuncSetAttribute(ao_mma_kernel, cudaFuncAttributeMaxDynamicSharedMemorySize, SMEM_TOT);
    int nsm = 148;
    cudaDeviceGetAttribute(&nsm, cudaDevAttrMultiProcessorCount, 0);

    zero_cnt_kernel<<<1, 32>>>();
    bin_kernel<<<BN / 512, 512>>>(s);
    ui_kernel<<<B_ / 8, 128>>>(u, iv, uiW0, uib0, uiW1, uib1);
    ao_mma_kernel<<<nsm, 512, SMEM_TOT>>>(a, o, aoW0, aob0, aoW1, aob1, out);
}

// round 16
// speedup vs baseline: 1.3123x; 1.3123x over previous
#include <cuda_runtime.h>
#include <cuda_bf16.h>

#define B_    8192
#define NPAIR 32
#define BN    (B_ * NPAIR)
#define RREL  3
#define KP    136            // padded bf16 row stride (conflict-free for ldmatrix)
#define CH    64             // items per chunk (per warp-group)

__device__ float g_ui[B_ * 64];
__device__ int   g_cnt[RREL];
__device__ int   g_items[RREL * BN];

__device__ __forceinline__ float lrelu(float x) { return x >= 0.f ? x : 0.01f * x; }

// Truncation-based 2-way bf16 split: hi = bit-truncated bf16 (exact residual),
// lo = rn(x - hi). Pair error <= 2^-17 |x|.
__device__ __forceinline__ void split2(float x0, float x1, unsigned& hi, unsigned& lo) {
    unsigned u0 = __float_as_uint(x0), u1 = __float_as_uint(x1);
    hi = __byte_perm(u0, u1, 0x7632);
    float l0 = x0 - __uint_as_float(u0 & 0xFFFF0000u);
    float l1 = x1 - __uint_as_float(u1 & 0xFFFF0000u);
    asm("cvt.rn.bf16x2.f32 %0, %1, %2;" : "=r"(lo) : "f"(l1), "f"(l0));
}

__device__ __forceinline__ unsigned smem_u32(const void* p) {
    unsigned a;
    asm("{ .reg .u64 t; cvta.to.shared.u64 t, %1; cvt.u32.u64 %0, t; }" : "=r"(a) : "l"(p));
    return a;
}

#define MMA(d, a, b) \
    asm volatile("mma.sync.aligned.m16n8k16.row.col.f32.bf16.bf16.f32 " \
        "{%0,%1,%2,%3}, {%4,%5,%6,%7}, {%8,%9}, {%0,%1,%2,%3};" \
        : "+f"((d)[0]), "+f"((d)[1]), "+f"((d)[2]), "+f"((d)[3]) \
        : "r"((a)[0]), "r"((a)[1]), "r"((a)[2]), "r"((a)[3]), "r"((b)[0]), "r"((b)[1]))

#define LDSM4(r0, r1, r2, r3, addr) \
    asm volatile("ldmatrix.sync.aligned.m8n8.x4.shared.b16 {%0,%1,%2,%3}, [%4];" \
        : "=r"(r0), "=r"(r1), "=r"(r2), "=r"(r3) : "r"(addr))

#define BARG(id) asm volatile("bar.sync %0, 256;" :: "r"(id) : "memory")

// ---------------- kernel A: ui branch (unchanged, passing) ----------------
__global__ __launch_bounds__(128) void ui_kernel(
    const float* __restrict__ u, const float* __restrict__ iv,
    const float* __restrict__ W0, const float* __restrict__ b0,
    const float* __restrict__ W1, const float* __restrict__ b1)
{
    __shared__ float sx[8][128];
    __shared__ float sh[8][128];
    int tid = threadIdx.x;
    int row0 = blockIdx.x * 8;
    #pragma unroll
    for (int rr = 0; rr < 8; rr++) {
        int row = row0 + rr;
        sx[rr][tid] = (tid < 64) ? u[row * 64 + tid] : iv[row * 64 + tid - 64];
    }
    __syncthreads();
    float acc[8];
    #pragma unroll
    for (int rr = 0; rr < 8; rr++) acc[rr] = 0.f;
    #pragma unroll 4
    for (int k = 0; k < 128; k++) {
        float w = W0[k * 128 + tid];
        #pragma unroll
        for (int rr = 0; rr < 8; rr++) acc[rr] += sx[rr][k] * w;
    }
    float bb = b0[tid];
    #pragma unroll
    for (int rr = 0; rr < 8; rr++) sh[rr][tid] = lrelu(acc[rr] + bb);
    __syncthreads();
    int j = tid & 63, rb = (tid >> 6) * 4;
    float a2[4] = {0.f, 0.f, 0.f, 0.f};
    #pragma unroll 4
    for (int k = 0; k < 128; k++) {
        float w = W1[k * 64 + j];
        #pragma unroll
        for (int q = 0; q < 4; q++) a2[q] += sh[rb + q][k] * w;
    }
    float b2 = b1[j];
    #pragma unroll
    for (int q = 0; q < 4; q++) g_ui[(row0 + rb + q) * 64 + j] = lrelu(a2[q] + b2);
}

// ---------------- zero + bin kernels ----------------
__global__ void zero_cnt_kernel() {
    if (threadIdx.x < RREL) g_cnt[threadIdx.x] = 0;
}

__global__ __launch_bounds__(512) void bin_kernel(const void* __restrict__ s_raw)
{
    __shared__ int bc[RREL], bb[RREL], sis64;
    int tid = threadIdx.x;
    if (tid == 0) {
        const int* p = (const int*)s_raw;
        int any = 0;
        for (int q = 1; q < 257; q += 2) any |= p[q];
        sis64 = (any == 0);
        bc[0] = bc[1] = bc[2] = 0;
    }
    __syncthreads();
    int it = blockIdx.x * 512 + tid;
    const int* s32 = (const int*)s_raw;
    int sv = sis64 ? s32[2 * it] : s32[it];
    sv = min(max(sv, 0), RREL - 1);
    int pos = atomicAdd(&bc[sv], 1);
    __syncthreads();
    if (tid < RREL) bb[tid] = atomicAdd(&g_cnt[tid], bc[tid]);
    __syncthreads();
    g_items[sv * BN + bb[sv] + pos] = it;
}

// ---------------- kernel C: bf16 mma.sync AO branch, 2 anti-phased warp-groups ----------------
#define XBYTES    17408
#define W0H_OFF   69632
#define W0L_OFF   104448
#define W1H_OFF   139264
#define W1L_OFF   156672
#define SB0_OFF   174080
#define SB1_OFF   174592
#define SL_OFF    174848
#define SRED_OFF  175360
#define SMEM_TOT  177408

#define ROWSTEP16 (16 * KP * 2)   // 4352 bytes

// Batched gather: 4 independent LDG.128s, then convert+store, twice.
__device__ __forceinline__ void gather_rows(
    char* smem, unsigned xoff, const float* __restrict__ a_emb,
    const float* __restrict__ o_emb, const int* __restrict__ slg, int tg)
{
    int row = tg >> 2, q = tg & 3;
    int g = slg[row];
    int cb = q * 32;
    const float* src = (q < 2) ? a_emb + (size_t)max(g, 0) * 64 + cb
                               : o_emb + (size_t)max(g, 0) * 64 + (cb - 64);
    #pragma unroll
    for (int h = 0; h < 2; h++) {
        float4 v[4];
        #pragma unroll
        for (int i = 0; i < 4; i++)
            v[i] = (g >= 0) ? *(const float4*)(src + h * 16 + i * 4)
                            : make_float4(0.f, 0.f, 0.f, 0.f);
        #pragma unroll
        for (int i = 0; i < 4; i++) {
            unsigned h0, l0, h1, l1;
            split2(v[i].x, v[i].y, h0, l0);
            split2(v[i].z, v[i].w, h1, l1);
            int cc = cb + h * 16 + i * 4;
            unsigned d = xoff + (row * KP + cc) * 2;
            *(uint2*)(smem + d)          = make_uint2(h0, h1);
            *(uint2*)(smem + d + XBYTES) = make_uint2(l0, l1);
        }
    }
}

__global__ __launch_bounds__(512, 1) void ao_mma_kernel(
    const float* __restrict__ a_emb, const float* __restrict__ o_emb,
    const float* __restrict__ aoW0, const float* __restrict__ aob0,
    const float* __restrict__ aoW1, const float* __restrict__ aob1,
    float* __restrict__ out)
{
    extern __shared__ char smem[];
    unsigned sbase = smem_u32(smem);
    float* sb0 = (float*)(smem + SB0_OFF);
    float* sb1 = (float*)(smem + SB1_OFF);

    int tid = threadIdx.x, wid = tid >> 5, lane = tid & 31;
    int grp = wid >> 3;
    int wg  = wid & 7;
    int tg  = tid & 255;
    int gq = lane >> 2, t = lane & 3;
    int barid = 1 + grp;

    int*   slg   = (int*)(smem + SL_OFF) + grp * 64;
    float* sredg = (float*)(smem + SRED_OFF) + grp * 256;

    unsigned rowSel = (unsigned)(lane & 15);
    unsigned kSel   = (unsigned)((lane >> 4) << 3);

    int mrow  = (wg & 1) * 32;
    int ncol  = (wg >> 1) * 32;
    int ncol2 = (wg >> 1) * 16;

    unsigned xoff  = (unsigned)grp * (2 * XBYTES);
    unsigned xbase = sbase + xoff;
    unsigned aHiB  = xbase + ((mrow + rowSel) * KP + kSel) * 2;
    unsigned aLoB  = aHiB + XBYTES;
    unsigned b0HiB = sbase + W0H_OFF + ((ncol + rowSel) * KP + kSel) * 2;
    unsigned b0LoB = b0HiB + (W0L_OFF - W0H_OFF);
    unsigned b1HiB = sbase + W1H_OFF + ((ncol2 + rowSel) * KP + kSel) * 2;
    unsigned b1LoB = b1HiB + (W1L_OFF - W1H_OFF);

    int cnt[RREL], rs[RREL + 1];
    rs[0] = 0;
    #pragma unroll
    for (int r = 0; r < RREL; r++) {
        cnt[r] = g_cnt[r];
        rs[r + 1] = rs[r] + ((cnt[r] + CH - 1) / CH);
    }
    int tot = rs[RREL];
    int per = (tot + gridDim.x - 1) / gridDim.x;
    int c_lo = blockIdx.x * per, c_hi = min(tot, c_lo + per);

    for (int r = 0; r < RREL; r++) {
        int lo = max(c_lo, rs[r]), hi = min(c_hi, rs[r + 1]);
        if (lo >= hi) continue;

        // ---- anti-phase staging: grp1 stages weights; grp0 pre-gathers chunk `lo` ----
        if (grp == 1) {
            const float* w0g = aoW0 + (size_t)r * 16384;
            for (int idx = tg; idx < 8192; idx += 256) {
                int n = idx & 127, k = (idx >> 7) * 2;
                unsigned hi_, lo_;
                split2(w0g[k * 128 + n], w0g[(k + 1) * 128 + n], hi_, lo_);
                *(unsigned*)(smem + W0H_OFF + (n * KP + k) * 2) = hi_;
                *(unsigned*)(smem + W0L_OFF + (n * KP + k) * 2) = lo_;
            }
            const float* w1g = aoW1 + (size_t)r * 8192;
            for (int idx = tg; idx < 4096; idx += 256) {
                int o = idx & 63, h = (idx >> 6) * 2;
                unsigned hi_, lo_;
                split2(w1g[h * 64 + o], w1g[(h + 1) * 64 + o], hi_, lo_);
                *(unsigned*)(smem + W1H_OFF + (o * KP + h) * 2) = hi_;
                *(unsigned*)(smem + W1L_OFF + (o * KP + h) * 2) = lo_;
            }
            if (tg < 128) sb0[tg] = aob0[r * 128 + tg];
            if (tg < 64)  sb1[tg] = aob1[r * 64 + tg];
        } else {
            int ci = lo - rs[r];
            int base = ci * CH;
            int valid = min(CH, cnt[r] - base);
            if (tg < 64) slg[tg] = (tg < valid) ? g_items[r * BN + base + tg] : -1;
            BARG(1);
            gather_rows(smem, xoff, a_emb, o_emb, slg, tg);
        }
        __syncthreads();

        // ---- group-interleaved chunk loop (grp0 leads by one gather phase) ----
        for (int c = lo + grp; c < hi; c += 2) {
            int ci = c - rs[r];
            int base = ci * CH;
            int valid = min(CH, cnt[r] - base);

            if (!(grp == 0 && c == lo)) {
                if (tg < 64) slg[tg] = (tg < valid) ? g_items[r * BN + base + tg] : -1;
                BARG(barid);
                gather_rows(smem, xoff, a_emb, o_emb, slg, tg);
                BARG(barid);
            }

            // ---- GEMM1: D1[64,128] = X @ W0 (3-term split, term-major issue) ----
            float acc[2][4][4];
            #pragma unroll
            for (int i = 0; i < 2; i++)
                #pragma unroll
                for (int j = 0; j < 4; j++)
                    #pragma unroll
                    for (int q = 0; q < 4; q++) acc[i][j][q] = 0.f;

            #pragma unroll
            for (int kt = 0; kt < 8; kt++) {
                unsigned ko = (unsigned)kt * 32;
                unsigned ah[2][4], al[2][4], bh[4][2], bl[4][2];
                LDSM4(ah[0][0], ah[0][1], ah[0][2], ah[0][3], aHiB + ko);
                LDSM4(ah[1][0], ah[1][1], ah[1][2], ah[1][3], aHiB + ROWSTEP16 + ko);
                LDSM4(al[0][0], al[0][1], al[0][2], al[0][3], aLoB + ko);
                LDSM4(al[1][0], al[1][1], al[1][2], al[1][3], aLoB + ROWSTEP16 + ko);
                {
                    unsigned r0, r1, r2, r3;
                    LDSM4(r0, r1, r2, r3, b0HiB + ko);
                    bh[0][0] = r0; bh[1][0] = r1; bh[0][1] = r2; bh[1][1] = r3;
                    LDSM4(r0, r1, r2, r3, b0HiB + ROWSTEP16 + ko);
                    bh[2][0] = r0; bh[3][0] = r1; bh[2][1] = r2; bh[3][1] = r3;
                    LDSM4(r0, r1, r2, r3, b0LoB + ko);
                    bl[0][0] = r0; bl[1][0] = r1; bl[0][1] = r2; bl[1][1] = r3;
                    LDSM4(r0, r1, r2, r3, b0LoB + ROWSTEP16 + ko);
                    bl[2][0] = r0; bl[3][0] = r1; bl[2][1] = r2; bl[3][1] = r3;
                }
                #pragma unroll
                for (int na = 0; na < 4; na++) {
                    MMA(acc[0][na], ah[0], bh[na]);
                    MMA(acc[1][na], ah[1], bh[na]);
                }
                #pragma unroll
                for (int na = 0; na < 4; na++) {
                    MMA(acc[0][na], ah[0], bl[na]);
                    MMA(acc[1][na], ah[1], bl[na]);
                }
                #pragma unroll
                for (int na = 0; na < 4; na++) {
                    MMA(acc[0][na], al[0], bh[na]);
                    MMA(acc[1][na], al[1], bh[na]);
                }
            }
            BARG(barid);   // all X reads done before overwrite with H

            // ---- epilogue 1: H = lrelu(D1 + b0), split in place of X ----
            #pragma unroll
            for (int ma = 0; ma < 2; ma++) {
                int rr0 = mrow + ma * 16 + gq;
                #pragma unroll
                for (int na = 0; na < 4; na++) {
                    int cc = ncol + na * 8 + 2 * t;
                    float h0 = lrelu(acc[ma][na][0] + sb0[cc]);
                    float h1 = lrelu(acc[ma][na][1] + sb0[cc + 1]);
                    float h2 = lrelu(acc[ma][na][2] + sb0[cc]);
                    float h3 = lrelu(acc[ma][na][3] + sb0[cc + 1]);
                    unsigned hi_, lo_;
                    unsigned d = xoff + (rr0 * KP + cc) * 2;
                    split2(h0, h1, hi_, lo_);
                    *(unsigned*)(smem + d)          = hi_;
                    *(unsigned*)(smem + d + XBYTES) = lo_;
                    split2(h2, h3, hi_, lo_);
                    unsigned d2 = d + 8 * KP * 2;
                    *(unsigned*)(smem + d2)          = hi_;
                    *(unsigned*)(smem + d2 + XBYTES) = lo_;
                }
            }
            BARG(barid);

            // ---- GEMM2: D2[64,64] = H @ W1 (term-major issue) ----
            float acc2[2][2][4];
            #pragma unroll
            for (int i = 0; i < 2; i++)
                #pragma unroll
                for (int j = 0; j < 2; j++)
                    #pragma unroll
                    for (int q = 0; q < 4; q++) acc2[i][j][q] = 0.f;

            #pragma unroll
            for (int kt = 0; kt < 8; kt++) {
                unsigned ko = (unsigned)kt * 32;
                unsigned ah[2][4], al[2][4], bh[2][2], bl[2][2];
                LDSM4(ah[0][0], ah[0][1], ah[0][2], ah[0][3], aHiB + ko);
                LDSM4(ah[1][0], ah[1][1], ah[1][2], ah[1][3], aHiB + ROWSTEP16 + ko);
                LDSM4(al[0][0], al[0][1], al[0][2], al[0][3], aLoB + ko);
                LDSM4(al[1][0], al[1][1], al[1][2], al[1][3], aLoB + ROWSTEP16 + ko);
                {
                    unsigned r0, r1, r2, r3;
                    LDSM4(r0, r1, r2, r3, b1HiB + ko);
                    bh[0][0] = r0; bh[1][0] = r1; bh[0][1] = r2; bh[1][1] = r3;
                    LDSM4(r0, r1, r2, r3, b1LoB + ko);
                    bl[0][0] = r0; bl[1][0] = r1; bl[0][1] = r2; bl[1][1] = r3;
                }
                #pragma unroll
                for (int na = 0; na < 2; na++) {
                    MMA(acc2[0][na], ah[0], bh[na]);
                    MMA(acc2[1][na], ah[1], bh[na]);
                }
                #pragma unroll
                for (int na = 0; na < 2; na++) {
                    MMA(acc2[0][na], ah[0], bl[na]);
                    MMA(acc2[1][na], ah[1], bl[na]);
                }
                #pragma unroll
                for (int na = 0; na < 2; na++) {
                    MMA(acc2[0][na], al[0], bh[na]);
                    MMA(acc2[1][na], al[1], bh[na]);
                }
            }

            // ---- epilogue 2: o = lrelu(D2 + b1); partial dot with ui; reduce ----
            #pragma unroll
            for (int ma = 0; ma < 2; ma++) {
                #pragma unroll
                for (int half = 0; half < 2; half++) {
                    int row = mrow + ma * 16 + gq + half * 8;
                    int g = slg[row];
                    const float* uiP = g_ui + (size_t)(max(g, 0) >> 5) * 64;
                    float p = 0.f;
                    #pragma unroll
                    for (int na = 0; na < 2; na++) {
                        int cc = ncol2 + na * 8 + 2 * t;
                        float2 uv = *(const float2*)(uiP + cc);
                        float o0 = lrelu(acc2[ma][na][half * 2]     + sb1[cc]);
                        float o1 = lrelu(acc2[ma][na][half * 2 + 1] + sb1[cc + 1]);
                        p += o0 * uv.x + o1 * uv.y;
                    }
                    p += __shfl_xor_sync(0xffffffffu, p, 1);
                    p += __shfl_xor_sync(0xffffffffu, p, 2);
                    if (t == 0) sredg[row * 4 + (wg >> 1)] = p;
                }
            }
            BARG(barid);
            if (tg < 64) {
                int g = slg[tg];
                if (g >= 0)
                    out[g] = sredg[tg * 4] + sredg[tg * 4 + 1]
                           + sredg[tg * 4 + 2] + sredg[tg * 4 + 3];
            }
            BARG(barid);
        }
        __syncthreads();
    }
}

// ---------------- launch ----------------
extern "C" void kernel_launch(void* const* d_in, const int* in_sizes, int n_in,
                              void* d_out, int out_size)
{
    const float* u    = (const float*)d_in[0];
    const float* iv   = (const float*)d_in[1];
    const float* a    = (const float*)d_in[2];
    const float* o    = (const float*)d_in[3];
    const void*  s    = d_in[4];
    const float* aoW0 = (const float*)d_in[5];
    const float* aob0 = (const float*)d_in[6];
    const float* aoW1 = (const float*)d_in[7];
    const float* aob1 = (const float*)d_in[8];
    const float* uiW0 = (const float*)d_in[9];
    const float* uib0 = (const float*)d_in[10];
    const float* uiW1 = (const float*)d_in[11];
    const float* uib1 = (const float*)d_in[12];
    float* out = (float*)d_out;

    cudaFuncSetAttribute(ao_mma_kernel, cudaFuncAttributeMaxDynamicSharedMemorySize, SMEM_TOT);
    int nsm = 148;
    cudaDeviceGetAttribute(&nsm, cudaDevAttrMultiProcessorCount, 0);

    zero_cnt_kernel<<<1, 32>>>();
    bin_kernel<<<BN / 512, 512>>>(s);
    ui_kernel<<<B_ / 8, 128>>>(u, iv, uiW0, uib0, uiW1, uib1);
    ao_mma_kernel<<<nsm, 512, SMEM_TOT>>>(a, o, aoW0, aob0, aoW1, aob1, out);
}